// round 1
// baseline (speedup 1.0000x reference)
#include <cuda_runtime.h>
#include <cuda_bf16.h>

// Problem constants (fixed by reference setup_inputs)
#define N_B      32
#define N_C      3
#define HW       4096      // 64*64
#define N_EMBD   896
#define INNER    128       // 896 / 7
#define N_LVL    7
#define N_CLS    1000
#define ROOT_OFF (6 * INNER)   // 768

// Scratch: root_avg vectors v[b][j]  (no cudaMalloc allowed)
__device__ float g_v[N_B * INNER];

// ---------------------------------------------------------------------------
// Kernel 1: per-batch channel means + root-embedding vector v[b][0:128]
//   mean_x[b][c] = mean over H,W of x[b,c,:,:]
//   v[b][j] = emb_b[768+j] + sum_{r=0..20} mean_x[b][r%3] * emb_w[r*896 + 768 + j]
// grid = 32 blocks (one per batch), 256 threads
// ---------------------------------------------------------------------------
__global__ __launch_bounds__(256) void k_mean_v(
    const float* __restrict__ x,
    const float* __restrict__ emb_w,
    const float* __restrict__ emb_b)
{
    const int b   = blockIdx.x;
    const int tid = threadIdx.x;
    const float* xb = x + (size_t)b * (N_C * HW);

    // Strided partial sums per channel (coalesced: consecutive tid -> consecutive i)
    float s0 = 0.f, s1 = 0.f, s2 = 0.f;
    #pragma unroll 4
    for (int i = tid; i < HW; i += 256) {
        s0 += xb[i];
        s1 += xb[HW + i];
        s2 += xb[2 * HW + i];
    }

    __shared__ float r0[256], r1[256], r2[256];
    r0[tid] = s0; r1[tid] = s1; r2[tid] = s2;
    __syncthreads();
    #pragma unroll
    for (int off = 128; off > 0; off >>= 1) {
        if (tid < off) {
            r0[tid] += r0[tid + off];
            r1[tid] += r1[tid + off];
            r2[tid] += r2[tid + off];
        }
        __syncthreads();
    }

    __shared__ float coef[N_C];
    if (tid == 0) {
        coef[0] = r0[0] * (1.0f / HW);
        coef[1] = r1[0] * (1.0f / HW);
        coef[2] = r2[0] * (1.0f / HW);
    }
    __syncthreads();

    if (tid < INNER) {
        float v = emb_b[ROOT_OFF + tid];
        #pragma unroll
        for (int r = 0; r < N_LVL * N_C; r++) {
            v += coef[r % N_C] * emb_w[r * N_EMBD + ROOT_OFF + tid];
        }
        g_v[b * INNER + tid] = v;
    }
}

// ---------------------------------------------------------------------------
// Kernel 2: out[b][k] = cls_b[k] + sum_j v[b][j] * cls_w[j*1000 + k]
// grid = (8 k-chunks of 125, 4 batch-groups of 8), 128 threads.
// Each weight load is reused across 8 batches (register accumulators);
// cls_w reads are coalesced across threads (consecutive k).
// ---------------------------------------------------------------------------
__global__ __launch_bounds__(128) void k_out(
    const float* __restrict__ cls_w,
    const float* __restrict__ cls_b,
    float* __restrict__ out)
{
    const int tid = threadIdx.x;
    const int k   = blockIdx.x * 125 + tid;     // 8 * 125 = 1000
    const int b0  = blockIdx.y * 8;             // 4 * 8   = 32

    __shared__ float sv[8][INNER];
    for (int i = tid; i < 8 * INNER; i += 128)
        sv[i / INNER][i % INNER] = g_v[b0 * INNER + i];
    __syncthreads();

    if (tid >= 125) return;   // k in [0, 1000)

    const float cb = cls_b[k];
    float acc[8];
    #pragma unroll
    for (int q = 0; q < 8; q++) acc[q] = cb;

    #pragma unroll 8
    for (int j = 0; j < INNER; j++) {
        const float w = cls_w[j * N_CLS + k];
        #pragma unroll
        for (int q = 0; q < 8; q++) acc[q] += sv[q][j] * w;
    }

    #pragma unroll
    for (int q = 0; q < 8; q++)
        out[(size_t)(b0 + q) * N_CLS + k] = acc[q];
}

// ---------------------------------------------------------------------------
// Launch. Inputs (metadata order): x, emb_w, emb_b, cls_w, cls_b. Output f32.
// Graph-capturable: kernel launches only, no allocs, no syncs.
// ---------------------------------------------------------------------------
extern "C" void kernel_launch(void* const* d_in, const int* in_sizes, int n_in,
                              void* d_out, int out_size)
{
    const float* x     = (const float*)d_in[0];
    const float* emb_w = (const float*)d_in[1];
    const float* emb_b = (const float*)d_in[2];
    const float* cls_w = (const float*)d_in[3];
    const float* cls_b = (const float*)d_in[4];
    float* out = (float*)d_out;

    k_mean_v<<<N_B, 256>>>(x, emb_w, emb_b);
    k_out<<<dim3(8, 4), 128>>>(cls_w, cls_b, out);
}

// round 2
// speedup vs baseline: 1.6750x; 1.6750x over previous
#include <cuda_runtime.h>
#include <cuda_bf16.h>

// Problem constants (fixed by reference setup_inputs)
#define N_B      32
#define N_C      3
#define HW       4096      // 64*64
#define HW4      1024      // HW / 4 (float4 count per channel)
#define N_EMBD   896
#define INNER    128       // 896 / 7
#define N_LVL    7
#define N_CLS    1000
#define ROOT_OFF 768       // 6 * INNER

// Scratch (__device__ globals; allocations forbidden)
__device__ float  g_coef[N_B * 4];   // per-batch channel means (padded stride 4)
__device__ float4 g_P[N_CLS];        // per-class {A, W0, W1, W2}

// ---------------------------------------------------------------------------
// k_prep: 40 blocks x 512 threads.
//  blocks 0..31  : batch b = blockIdx.x — channel means of x[b] -> g_coef
//  blocks 32..39 : k-chunk kx = blockIdx.x-32 — batch-independent classifier
//                  collapse: g_P[k] = {A, W0, W1, W2}
// ---------------------------------------------------------------------------
__global__ __launch_bounds__(512) void k_prep(
    const float* __restrict__ x,
    const float* __restrict__ emb_w,
    const float* __restrict__ emb_b,
    const float* __restrict__ cls_w)
{
    const int tid = threadIdx.x;
    const int blk = blockIdx.x;

    if (blk < N_B) {
        // ---- per-batch channel means (float4, 6 loads/thread) ----
        const float4* xb = (const float4*)(x + (size_t)blk * (N_C * HW));
        float s0, s1, s2;
        {
            float4 a0 = xb[0 * HW4 + tid],        a1 = xb[0 * HW4 + 512 + tid];
            float4 b0 = xb[1 * HW4 + tid],        b1 = xb[1 * HW4 + 512 + tid];
            float4 c0 = xb[2 * HW4 + tid],        c1 = xb[2 * HW4 + 512 + tid];
            s0 = (a0.x + a0.y + a0.z + a0.w) + (a1.x + a1.y + a1.z + a1.w);
            s1 = (b0.x + b0.y + b0.z + b0.w) + (b1.x + b1.y + b1.z + b1.w);
            s2 = (c0.x + c0.y + c0.z + c0.w) + (c1.x + c1.y + c1.z + c1.w);
        }
        // warp reduce
        #pragma unroll
        for (int off = 16; off > 0; off >>= 1) {
            s0 += __shfl_xor_sync(0xFFFFFFFFu, s0, off);
            s1 += __shfl_xor_sync(0xFFFFFFFFu, s1, off);
            s2 += __shfl_xor_sync(0xFFFFFFFFu, s2, off);
        }
        __shared__ float wr[16][3];
        const int wid = tid >> 5, lane = tid & 31;
        if (lane == 0) { wr[wid][0] = s0; wr[wid][1] = s1; wr[wid][2] = s2; }
        __syncthreads();
        if (tid < 16) {
            float a0 = wr[tid][0], a1 = wr[tid][1], a2 = wr[tid][2];
            #pragma unroll
            for (int off = 8; off > 0; off >>= 1) {
                a0 += __shfl_xor_sync(0xFFFFu, a0, off);
                a1 += __shfl_xor_sync(0xFFFFu, a1, off);
                a2 += __shfl_xor_sync(0xFFFFu, a2, off);
            }
            if (tid == 0) {
                g_coef[blk * 4 + 0] = a0 * (1.0f / HW);
                g_coef[blk * 4 + 1] = a1 * (1.0f / HW);
                g_coef[blk * 4 + 2] = a2 * (1.0f / HW);
            }
        }
    } else {
        // ---- batch-independent classifier collapse ----
        const int kx = blk - N_B;                 // 0..7 (125 classes each)
        __shared__ float sw[4][INNER];            // [emb_b, wsum0, wsum1, wsum2][j]
        __shared__ float part[4][4][INNER];       // [jq][A/W0/W1/W2][t]

        if (tid < INNER) {
            float w0 = 0.f, w1 = 0.f, w2 = 0.f;
            #pragma unroll
            for (int l = 0; l < N_LVL; l++) {
                w0 += emb_w[(3 * l + 0) * N_EMBD + ROOT_OFF + tid];
                w1 += emb_w[(3 * l + 1) * N_EMBD + ROOT_OFF + tid];
                w2 += emb_w[(3 * l + 2) * N_EMBD + ROOT_OFF + tid];
            }
            sw[0][tid] = emb_b[ROOT_OFF + tid];
            sw[1][tid] = w0;  sw[2][tid] = w1;  sw[3][tid] = w2;
        }
        __syncthreads();

        const int t  = tid & 127;                 // k-lane (0..124 active)
        const int jq = tid >> 7;                  // j-quarter (0..3)
        float aA = 0.f, a0 = 0.f, a1 = 0.f, a2 = 0.f;
        if (t < 125) {
            const int k     = kx * 125 + t;
            const int jbase = jq * 32;
            #pragma unroll
            for (int jj = 0; jj < 32; jj++) {
                const int j = jbase + jj;
                const float w = cls_w[j * N_CLS + k];
                aA += sw[0][j] * w;
                a0 += sw[1][j] * w;
                a1 += sw[2][j] * w;
                a2 += sw[3][j] * w;
            }
        }
        part[jq][0][t] = aA;  part[jq][1][t] = a0;
        part[jq][2][t] = a1;  part[jq][3][t] = a2;
        __syncthreads();

        if (tid < 125) {
            float A  = part[0][0][tid] + part[1][0][tid] + part[2][0][tid] + part[3][0][tid];
            float W0 = part[0][1][tid] + part[1][1][tid] + part[2][1][tid] + part[3][1][tid];
            float W1 = part[0][2][tid] + part[1][2][tid] + part[2][2][tid] + part[3][2][tid];
            float W2 = part[0][3][tid] + part[1][3][tid] + part[2][3][tid] + part[3][3][tid];
            g_P[kx * 125 + tid] = make_float4(A, W0, W1, W2);
        }
    }
}

// ---------------------------------------------------------------------------
// k_final: out[b,k] = cls_b[k] + A[k] + c0*W0[k] + c1*W1[k] + c2*W2[k]
// grid (8 k-chunks, 32 batches) x 128 threads — one output per thread.
// ---------------------------------------------------------------------------
__global__ __launch_bounds__(128) void k_final(
    const float* __restrict__ cls_b,
    float* __restrict__ out)
{
    const int t = threadIdx.x;
    if (t >= 125) return;
    const int k = blockIdx.x * 125 + t;
    const int b = blockIdx.y;

    const float4 P  = g_P[k];
    const float  c0 = g_coef[b * 4 + 0];
    const float  c1 = g_coef[b * 4 + 1];
    const float  c2 = g_coef[b * 4 + 2];

    out[(size_t)b * N_CLS + k] = cls_b[k] + P.x + c0 * P.y + c1 * P.z + c2 * P.w;
}

// ---------------------------------------------------------------------------
// Launch. Inputs (metadata order): x, emb_w, emb_b, cls_w, cls_b. Output f32.
// Graph-capturable: kernel launches only, no allocs, no syncs.
// ---------------------------------------------------------------------------
extern "C" void kernel_launch(void* const* d_in, const int* in_sizes, int n_in,
                              void* d_out, int out_size)
{
    const float* x     = (const float*)d_in[0];
    const float* emb_w = (const float*)d_in[1];
    const float* emb_b = (const float*)d_in[2];
    const float* cls_w = (const float*)d_in[3];
    const float* cls_b = (const float*)d_in[4];
    float* out = (float*)d_out;

    k_prep<<<N_B + 8, 512>>>(x, emb_w, emb_b, cls_w);
    k_final<<<dim3(8, N_B), 128>>>(cls_b, out);
}

// round 3
// speedup vs baseline: 1.7070x; 1.0191x over previous
#include <cuda_runtime.h>
#include <cuda_bf16.h>

// Problem constants (fixed by reference setup_inputs)
#define N_B      32
#define N_C      3
#define HW       4096      // 64*64
#define HW4      1024      // HW / 4 (float4 count per channel)
#define N_EMBD   896
#define INNER    128       // 896 / 7
#define N_LVL    7
#define N_CLS    1000
#define ROOT_OFF 768       // 6 * INNER

#define NBLK     40        // 32 mean-blocks + 8 classifier-collapse blocks
#define NTHR     512
#define OUT_PER_BLK 800    // 32000 / 40

// Scratch (__device__ globals; allocations forbidden)
__device__ float  g_coef[N_B * 4];             // per-batch channel means
__device__ float4 g_P[N_CLS];                  // per-class {A, W0, W1, W2}
__device__ unsigned long long g_ctr;           // monotonic barrier counter (replay-safe)

// ---------------------------------------------------------------------------
// Single fused kernel. Grid = 40 x 512.
//  Phase 1:
//    blocks 0..31  : batch b — channel means of x[b] -> g_coef
//    blocks 32..39 : k-chunk — batch-independent collapse g_P[k]={A,W0,W1,W2}
//  Grid barrier (generation-counting, safe across graph replays)
//  Phase 2: each block writes 800 outputs: out[b,k]=cls_b[k]+A+c0*W0+c1*W1+c2*W2
// ---------------------------------------------------------------------------
__global__ __launch_bounds__(NTHR) void k_all(
    const float* __restrict__ x,
    const float* __restrict__ emb_w,
    const float* __restrict__ emb_b,
    const float* __restrict__ cls_w,
    const float* __restrict__ cls_b,
    float* __restrict__ out)
{
    const int tid = threadIdx.x;
    const int blk = blockIdx.x;

    // ================= Phase 1 =================
    if (blk < N_B) {
        // ---- per-batch channel means (float4, 6 loads/thread) ----
        const float4* xb = (const float4*)(x + (size_t)blk * (N_C * HW));
        float s0, s1, s2;
        {
            float4 a0 = xb[0 * HW4 + tid], a1 = xb[0 * HW4 + 512 + tid];
            float4 b0 = xb[1 * HW4 + tid], b1 = xb[1 * HW4 + 512 + tid];
            float4 c0 = xb[2 * HW4 + tid], c1 = xb[2 * HW4 + 512 + tid];
            s0 = (a0.x + a0.y + a0.z + a0.w) + (a1.x + a1.y + a1.z + a1.w);
            s1 = (b0.x + b0.y + b0.z + b0.w) + (b1.x + b1.y + b1.z + b1.w);
            s2 = (c0.x + c0.y + c0.z + c0.w) + (c1.x + c1.y + c1.z + c1.w);
        }
        #pragma unroll
        for (int off = 16; off > 0; off >>= 1) {
            s0 += __shfl_xor_sync(0xFFFFFFFFu, s0, off);
            s1 += __shfl_xor_sync(0xFFFFFFFFu, s1, off);
            s2 += __shfl_xor_sync(0xFFFFFFFFu, s2, off);
        }
        __shared__ float wr[16][3];
        const int wid = tid >> 5, lane = tid & 31;
        if (lane == 0) { wr[wid][0] = s0; wr[wid][1] = s1; wr[wid][2] = s2; }
        __syncthreads();
        if (tid < 16) {
            float a0 = wr[tid][0], a1 = wr[tid][1], a2 = wr[tid][2];
            #pragma unroll
            for (int off = 8; off > 0; off >>= 1) {
                a0 += __shfl_xor_sync(0xFFFFu, a0, off);
                a1 += __shfl_xor_sync(0xFFFFu, a1, off);
                a2 += __shfl_xor_sync(0xFFFFu, a2, off);
            }
            if (tid == 0) {
                g_coef[blk * 4 + 0] = a0 * (1.0f / HW);
                g_coef[blk * 4 + 1] = a1 * (1.0f / HW);
                g_coef[blk * 4 + 2] = a2 * (1.0f / HW);
            }
        }
    } else {
        // ---- batch-independent classifier collapse ----
        const int kx = blk - N_B;                 // 0..7 (125 classes each)
        __shared__ float sw[4][INNER];            // [emb_b, wsum0, wsum1, wsum2][j]
        __shared__ float part[4][4][INNER];       // [jq][A/W0/W1/W2][t]

        if (tid < INNER) {
            float w0 = 0.f, w1 = 0.f, w2 = 0.f;
            #pragma unroll
            for (int l = 0; l < N_LVL; l++) {
                w0 += emb_w[(3 * l + 0) * N_EMBD + ROOT_OFF + tid];
                w1 += emb_w[(3 * l + 1) * N_EMBD + ROOT_OFF + tid];
                w2 += emb_w[(3 * l + 2) * N_EMBD + ROOT_OFF + tid];
            }
            sw[0][tid] = emb_b[ROOT_OFF + tid];
            sw[1][tid] = w0;  sw[2][tid] = w1;  sw[3][tid] = w2;
        }
        __syncthreads();

        const int t  = tid & 127;                 // k-lane (0..124 active)
        const int jq = tid >> 7;                  // j-quarter (0..3)
        float aA = 0.f, a0 = 0.f, a1 = 0.f, a2 = 0.f;
        if (t < 125) {
            const int k     = kx * 125 + t;
            const int jbase = jq * 32;
            #pragma unroll
            for (int jj = 0; jj < 32; jj++) {
                const int j = jbase + jj;
                const float w = cls_w[j * N_CLS + k];
                aA += sw[0][j] * w;
                a0 += sw[1][j] * w;
                a1 += sw[2][j] * w;
                a2 += sw[3][j] * w;
            }
        }
        part[jq][0][t] = aA;  part[jq][1][t] = a0;
        part[jq][2][t] = a1;  part[jq][3][t] = a2;
        __syncthreads();

        if (tid < 125) {
            float A  = part[0][0][tid] + part[1][0][tid] + part[2][0][tid] + part[3][0][tid];
            float W0 = part[0][1][tid] + part[1][1][tid] + part[2][1][tid] + part[3][1][tid];
            float W1 = part[0][2][tid] + part[1][2][tid] + part[2][2][tid] + part[3][2][tid];
            float W2 = part[0][3][tid] + part[1][3][tid] + part[2][3][tid] + part[3][3][tid];
            g_P[kx * 125 + tid] = make_float4(A, W0, W1, W2);
        }
    }

    // ================= Grid barrier (replay-safe generation counting) ========
    // Monotonic counter: arrival index old in [g*NBLK, (g+1)*NBLK); generation
    // g = old/NBLK; wait until ctr >= (g+1)*NBLK. No reset needed across graph
    // replays. All 40 blocks are co-resident (40 <= 148 SMs) -> no deadlock.
    __syncthreads();               // all threads of block done with phase 1
    if (tid == 0) {
        __threadfence();           // release phase-1 writes
        unsigned long long old = atomicAdd(&g_ctr, 1ULL);
        unsigned long long target = (old / NBLK + 1ULL) * NBLK;
        while (*(volatile unsigned long long*)&g_ctr < target) { }
        __threadfence();           // acquire other blocks' writes
    }
    __syncthreads();

    // ================= Phase 2: outputs =================
    // Block blk writes outputs [blk*800, blk*800+800).
    const int base = blk * OUT_PER_BLK;
    #pragma unroll
    for (int i = tid; i < OUT_PER_BLK; i += NTHR) {
        const int idx = base + i;
        const int b   = idx / N_CLS;
        const int k   = idx - b * N_CLS;
        const float4 P  = g_P[k];
        const float  c0 = g_coef[b * 4 + 0];
        const float  c1 = g_coef[b * 4 + 1];
        const float  c2 = g_coef[b * 4 + 2];
        out[idx] = cls_b[k] + P.x + fmaf(c0, P.y, fmaf(c1, P.z, c2 * P.w));
    }
}

// ---------------------------------------------------------------------------
// Launch. Inputs (metadata order): x, emb_w, emb_b, cls_w, cls_b. Output f32.
// Graph-capturable: one kernel launch, no allocs, no syncs.
// ---------------------------------------------------------------------------
extern "C" void kernel_launch(void* const* d_in, const int* in_sizes, int n_in,
                              void* d_out, int out_size)
{
    const float* x     = (const float*)d_in[0];
    const float* emb_w = (const float*)d_in[1];
    const float* emb_b = (const float*)d_in[2];
    const float* cls_w = (const float*)d_in[3];
    const float* cls_b = (const float*)d_in[4];
    float* out = (float*)d_out;

    k_all<<<NBLK, NTHR>>>(x, emb_w, emb_b, cls_w, cls_b, out);
}

// round 4
// speedup vs baseline: 1.9706x; 1.1544x over previous
#include <cuda_runtime.h>
#include <cuda_bf16.h>

// Problem constants (fixed by reference setup_inputs)
#define N_B      32
#define N_C      3
#define HW       4096      // 64*64
#define HW4      1024      // HW / 4
#define N_EMBD   896
#define INNER    128       // 896 / 7
#define N_LVL    7
#define N_CLS    1000
#define ROOT_OFF 768       // 6 * INNER

#define NBLK     40        // 32 mean blocks + 8 classifier blocks
#define NTHR     512
#define KCHUNK   125       // k per classifier block (8 * 125 = 1000)

// Scratch (__device__ globals; allocations forbidden). Counters are monotonic
// (never reset) => correct across the correctness call and every graph replay.
__device__ float g_coef[N_B * 4];
__device__ unsigned long long g_mean_ctr;   // +32 per launch (mean blocks)
__device__ unsigned long long g_cls_ctr;    // +8  per launch (classifier blocks)

// ---------------------------------------------------------------------------
// Single kernel, asymmetric roles:
//  blocks 0..31  (mean):  channel means -> g_coef, fence, arrive, EXIT.
//  blocks 32..39 (cls):   hoisted cls_w/cls_b loads overlapped with emb_w,
//                         collapse to {A+cls_b, W0,W1,W2} in SHARED,
//                         wait for this launch's 32 mean arrivals,
//                         write own 125 k x 32 b outputs directly.
// ---------------------------------------------------------------------------
__global__ __launch_bounds__(NTHR) void k_all(
    const float* __restrict__ x,
    const float* __restrict__ emb_w,
    const float* __restrict__ emb_b,
    const float* __restrict__ cls_w,
    const float* __restrict__ cls_b,
    float* __restrict__ out)
{
    const int tid = threadIdx.x;
    const int blk = blockIdx.x;

    if (blk < N_B) {
        // ======================= mean blocks =======================
        const float4* xb = (const float4*)(x + (size_t)blk * (N_C * HW));
        float s0, s1, s2;
        {
            float4 a0 = xb[0 * HW4 + tid], a1 = xb[0 * HW4 + 512 + tid];
            float4 b0 = xb[1 * HW4 + tid], b1 = xb[1 * HW4 + 512 + tid];
            float4 c0 = xb[2 * HW4 + tid], c1 = xb[2 * HW4 + 512 + tid];
            s0 = (a0.x + a0.y + a0.z + a0.w) + (a1.x + a1.y + a1.z + a1.w);
            s1 = (b0.x + b0.y + b0.z + b0.w) + (b1.x + b1.y + b1.z + b1.w);
            s2 = (c0.x + c0.y + c0.z + c0.w) + (c1.x + c1.y + c1.z + c1.w);
        }
        #pragma unroll
        for (int off = 16; off > 0; off >>= 1) {
            s0 += __shfl_xor_sync(0xFFFFFFFFu, s0, off);
            s1 += __shfl_xor_sync(0xFFFFFFFFu, s1, off);
            s2 += __shfl_xor_sync(0xFFFFFFFFu, s2, off);
        }
        __shared__ float wr[16][3];
        const int wid = tid >> 5, lane = tid & 31;
        if (lane == 0) { wr[wid][0] = s0; wr[wid][1] = s1; wr[wid][2] = s2; }
        __syncthreads();
        if (tid < 16) {
            float a0 = wr[tid][0], a1 = wr[tid][1], a2 = wr[tid][2];
            #pragma unroll
            for (int off = 8; off > 0; off >>= 1) {
                a0 += __shfl_xor_sync(0xFFFFu, a0, off);
                a1 += __shfl_xor_sync(0xFFFFu, a1, off);
                a2 += __shfl_xor_sync(0xFFFFu, a2, off);
            }
            if (tid == 0) {
                g_coef[blk * 4 + 0] = a0 * (1.0f / HW);
                g_coef[blk * 4 + 1] = a1 * (1.0f / HW);
                g_coef[blk * 4 + 2] = a2 * (1.0f / HW);
                __threadfence();                       // release coef
                atomicAdd(&g_mean_ctr, 1ULL);          // arrive
            }
        }
        return;                                        // mean blocks exit
    }

    // ======================= classifier blocks =======================
    const int kx = blk - N_B;                          // 0..7
    const int t  = tid & 127;                          // k-lane (0..124 active)
    const int jq = tid >> 7;                           // j-quarter (0..3)
    const int k  = kx * KCHUNK + t;
    const bool kv = (t < KCHUNK);

    // ---- HOIST: issue all global loads for this thread up front (one DRAM
    //      round, MLP=33) so they overlap the emb_w loads + syncs below.
    float wreg[32];
    float cbreg = 0.f;
    if (kv) {
        const int jbase = jq * 32;
        #pragma unroll
        for (int jj = 0; jj < 32; jj++)
            wreg[jj] = __ldg(&cls_w[(jbase + jj) * N_CLS + k]);
        if (jq == 0) cbreg = __ldg(&cls_b[k]);
    }

    __shared__ float  sw[4][INNER];                    // [bias, ws0, ws1, ws2][j]
    __shared__ float  part[4][4][INNER];               // [jq][A/W0/W1/W2][t]
    __shared__ float4 sP[KCHUNK];                      // {A+cls_b, W0, W1, W2}
    __shared__ float  scoef[N_B * 4];

    if (tid < INNER) {
        float w0 = 0.f, w1 = 0.f, w2 = 0.f;
        #pragma unroll
        for (int l = 0; l < N_LVL; l++) {
            w0 += emb_w[(3 * l + 0) * N_EMBD + ROOT_OFF + tid];
            w1 += emb_w[(3 * l + 1) * N_EMBD + ROOT_OFF + tid];
            w2 += emb_w[(3 * l + 2) * N_EMBD + ROOT_OFF + tid];
        }
        sw[0][tid] = emb_b[ROOT_OFF + tid];
        sw[1][tid] = w0;  sw[2][tid] = w1;  sw[3][tid] = w2;
    }
    __syncthreads();

    float aA = 0.f, a0 = 0.f, a1 = 0.f, a2 = 0.f;
    if (kv) {
        const int jbase = jq * 32;
        #pragma unroll
        for (int jj = 0; jj < 32; jj++) {
            const float w = wreg[jj];
            aA = fmaf(sw[0][jbase + jj], w, aA);
            a0 = fmaf(sw[1][jbase + jj], w, a0);
            a1 = fmaf(sw[2][jbase + jj], w, a1);
            a2 = fmaf(sw[3][jbase + jj], w, a2);
        }
    }
    part[jq][0][t] = (jq == 0) ? aA + cbreg : aA;      // fold cls_b into A
    part[jq][1][t] = a0;
    part[jq][2][t] = a1;
    part[jq][3][t] = a2;
    __syncthreads();

    if (tid < KCHUNK) {
        sP[tid] = make_float4(
            part[0][0][tid] + part[1][0][tid] + part[2][0][tid] + part[3][0][tid],
            part[0][1][tid] + part[1][1][tid] + part[2][1][tid] + part[3][1][tid],
            part[0][2][tid] + part[1][2][tid] + part[2][2][tid] + part[3][2][tid],
            part[0][3][tid] + part[1][3][tid] + part[2][3][tid] + part[3][3][tid]);
    }

    // ---- wait for THIS launch's 32 mean arrivals (generation from own ctr)
    __shared__ unsigned long long s_gen;
    if (tid == 0) {
        unsigned long long my = atomicAdd(&g_cls_ctr, 1ULL);   // 8 per launch
        unsigned long long gen = my >> 3;                       // launch index
        unsigned long long target = (gen + 1ULL) * N_B;
        while (*(volatile unsigned long long*)&g_mean_ctr < target) { }
        __threadfence();                                        // acquire coef
        s_gen = gen;                                            // (dummy use)
    }
    __syncthreads();

    if (tid < N_B * 4) scoef[tid] = g_coef[tid];
    __syncthreads();

    // ---- write own 4000 outputs: out[b, kx*125 + kl]
    #pragma unroll
    for (int i = tid; i < N_B * KCHUNK; i += NTHR) {
        const int b  = i / KCHUNK;
        const int kl = i - b * KCHUNK;
        const float4 P  = sP[kl];
        const float  c0 = scoef[b * 4 + 0];
        const float  c1 = scoef[b * 4 + 1];
        const float  c2 = scoef[b * 4 + 2];
        out[(size_t)b * N_CLS + kx * KCHUNK + kl] =
            P.x + fmaf(c0, P.y, fmaf(c1, P.z, c2 * P.w));
    }
}

// ---------------------------------------------------------------------------
// Launch. Inputs (metadata order): x, emb_w, emb_b, cls_w, cls_b. Output f32.
// Graph-capturable: one kernel launch, no allocs, no syncs.
// ---------------------------------------------------------------------------
extern "C" void kernel_launch(void* const* d_in, const int* in_sizes, int n_in,
                              void* d_out, int out_size)
{
    const float* x     = (const float*)d_in[0];
    const float* emb_w = (const float*)d_in[1];
    const float* emb_b = (const float*)d_in[2];
    const float* cls_w = (const float*)d_in[3];
    const float* cls_b = (const float*)d_in[4];
    float* out = (float*)d_out;

    k_all<<<NBLK, NTHR>>>(x, emb_w, emb_b, cls_w, cls_b, out);
}